// round 1
// baseline (speedup 1.0000x reference)
#include <cuda_runtime.h>
#include <math.h>

#define BATCH 65536
#define KCODES 1024
#define DIM 256

// f32 constants matching the reference's rounding:
// DECAY is python double 0.99 -> f32(0.99); (1.0-DECAY) is computed in double then cast.
#define DECAY_F 0.99f
#define OMD_F ((float)(1.0 - 0.99))     // 0.009999999776482582f

// ---- output layout: tuple flattened+concatenated in return order, f32 ----
#define OFF_ZQ   0
#define OFF_LOSS (BATCH * DIM)
#define OFF_PERP (BATCH * DIM + 1)
#define OFF_IDX  (BATCH * DIM + 2)
#define OFF_EMB  (OFF_IDX + BATCH)
#define OFF_ECS  (OFF_EMB + KCODES * DIM)
#define OFF_EMAW (OFF_ECS + KCODES)

// ---- device-global scratch (no allocations allowed) ----
__device__ float  g_esq[KCODES];
__device__ float  g_zsq[BATCH];
__device__ int    g_idx[BATCH];
__device__ float  g_cs[KCODES];
__device__ float  g_dw[KCODES * DIM];
__device__ double g_loss;
__device__ float  g_smoothed[KCODES];

// ============================================================
// Zero the accumulators used by atomics.
// ============================================================
__global__ void init_kernel() {
    int i = blockIdx.x * blockDim.x + threadIdx.x;
    if (i < KCODES * DIM) g_dw[i] = 0.0f;
    if (i < KCODES)       g_cs[i] = 0.0f;
    if (i == 0)           g_loss  = 0.0;
}

// ============================================================
// Row squared-norms for z_e (first BATCH rows) and embedding.
// One warp per row, float4 loads.
// ============================================================
__global__ void rowsq_kernel(const float* __restrict__ Z,
                             const float* __restrict__ E) {
    int row  = blockIdx.x * 8 + (threadIdx.x >> 5);
    int lane = threadIdx.x & 31;
    const float* src;
    float* dst;
    if (row < BATCH) {
        src = Z + (size_t)row * DIM;
        dst = g_zsq + row;
    } else {
        int r = row - BATCH;
        src = E + (size_t)r * DIM;
        dst = g_esq + r;
    }
    const float4* p = (const float4*)src;
    float4 v0 = p[lane * 2 + 0];
    float4 v1 = p[lane * 2 + 1];
    float s = v0.x * v0.x + v0.y * v0.y + v0.z * v0.z + v0.w * v0.w
            + v1.x * v1.x + v1.y * v1.y + v1.z * v1.z + v1.w * v1.w;
#pragma unroll
    for (int o = 16; o; o >>= 1) s += __shfl_down_sync(0xffffffffu, s, o);
    if (lane == 0) *dst = s;
}

// ============================================================
// Fused SGEMM + argmin:
//   dist[b,k] = (zsq[b] + esq[k]) - 2 * dot(z_b, e_k)
//   g_idx[b]  = argmin_k dist (first-occurrence tie-break, like jnp.argmin)
// 128x128 block tile, 16-deep K chunks, 8x8 per thread, 256 threads.
// Transposed smem tiles with stride 136 (conflict-free stores, 16B-aligned rows).
// ============================================================
#define BM 128
#define BN 128
#define BKT 16
#define LDA 136

__global__ __launch_bounds__(256, 2)
void argmin_kernel(const float* __restrict__ Z, const float* __restrict__ E) {
    __shared__ float As[BKT * LDA];
    __shared__ float Bs[BKT * LDA];

    const int tid = threadIdx.x;
    const int tr  = tid >> 4;   // 0..15 (row group)
    const int tc  = tid & 15;   // 0..15 (col group)
    const int rowBase = blockIdx.x * BM;

    float zs[8];
#pragma unroll
    for (int i = 0; i < 8; i++) zs[i] = g_zsq[rowBase + tr * 8 + i];

    float bestd[8];
    int   bestk[8];
#pragma unroll
    for (int i = 0; i < 8; i++) { bestd[i] = 3.4e38f; bestk[i] = 0; }

    for (int nt = 0; nt < KCODES / BN; nt++) {
        const int codeBase = nt * BN;

        float acc[8][8];
#pragma unroll
        for (int i = 0; i < 8; i++)
#pragma unroll
            for (int j = 0; j < 8; j++) acc[i][j] = 0.0f;

        for (int dt = 0; dt < DIM / BKT; dt++) {
            const int dBase = dt * BKT;
            // load A (z rows) and B (codes), transposed into smem
#pragma unroll
            for (int l = 0; l < 2; l++) {
                int t  = tid + l * 256;      // 0..511
                int r  = t >> 2;             // 0..127
                int c4 = t & 3;              // which float4 of the 16 cols
                float4 va = *(const float4*)(Z + (size_t)(rowBase + r) * DIM + dBase + c4 * 4);
                As[(c4 * 4 + 0) * LDA + r] = va.x;
                As[(c4 * 4 + 1) * LDA + r] = va.y;
                As[(c4 * 4 + 2) * LDA + r] = va.z;
                As[(c4 * 4 + 3) * LDA + r] = va.w;
                float4 vb = *(const float4*)(E + (size_t)(codeBase + r) * DIM + dBase + c4 * 4);
                Bs[(c4 * 4 + 0) * LDA + r] = vb.x;
                Bs[(c4 * 4 + 1) * LDA + r] = vb.y;
                Bs[(c4 * 4 + 2) * LDA + r] = vb.z;
                Bs[(c4 * 4 + 3) * LDA + r] = vb.w;
            }
            __syncthreads();

#pragma unroll
            for (int kk = 0; kk < BKT; kk++) {
                float4 a0 = *(const float4*)&As[kk * LDA + tr * 8 + 0];
                float4 a1 = *(const float4*)&As[kk * LDA + tr * 8 + 4];
                float4 b0 = *(const float4*)&Bs[kk * LDA + tc * 8 + 0];
                float4 b1 = *(const float4*)&Bs[kk * LDA + tc * 8 + 4];
                float a[8] = {a0.x, a0.y, a0.z, a0.w, a1.x, a1.y, a1.z, a1.w};
                float b[8] = {b0.x, b0.y, b0.z, b0.w, b1.x, b1.y, b1.z, b1.w};
#pragma unroll
                for (int i = 0; i < 8; i++)
#pragma unroll
                    for (int j = 0; j < 8; j++)
                        acc[i][j] += a[i] * b[j];
            }
            __syncthreads();
        }

        // argmin epilogue for this code tile (ascending j keeps first-index ties)
#pragma unroll
        for (int j = 0; j < 8; j++) {
            int   code = codeBase + tc * 8 + j;
            float esq  = g_esq[code];
#pragma unroll
            for (int i = 0; i < 8; i++) {
                float dist = (zs[i] + esq) - 2.0f * acc[i][j];
                if (dist < bestd[i]) { bestd[i] = dist; bestk[i] = code; }
            }
        }
    }

    // reduce across the 16 threads (tc) sharing each row; tie -> lower index
#pragma unroll
    for (int off = 8; off; off >>= 1) {
#pragma unroll
        for (int i = 0; i < 8; i++) {
            float od = __shfl_down_sync(0xffffffffu, bestd[i], off, 16);
            int   ok = __shfl_down_sync(0xffffffffu, bestk[i], off, 16);
            if (od < bestd[i] || (od == bestd[i] && ok < bestk[i])) {
                bestd[i] = od; bestk[i] = ok;
            }
        }
    }
    if (tc == 0) {
#pragma unroll
        for (int i = 0; i < 8; i++) g_idx[rowBase + tr * 8 + i] = bestk[i];
    }
}

// ============================================================
// Gather z_q, write z_q_st + float(indices), accumulate loss,
// cluster_size and dw (segment sums) via atomics. One warp per row.
// ============================================================
__global__ void gather_kernel(const float* __restrict__ Z,
                              const float* __restrict__ E,
                              float* __restrict__ out) {
    int warp = threadIdx.x >> 5;
    int lane = threadIdx.x & 31;
    int row  = blockIdx.x * 8 + warp;
    int ci   = g_idx[row];

    const float4* zp = (const float4*)(Z + (size_t)row * DIM);
    const float4* qp = (const float4*)(E + (size_t)ci * DIM);
    float4*       op = (float4*)(out + OFF_ZQ + (size_t)row * DIM);

    float sq = 0.0f;
#pragma unroll
    for (int l = 0; l < 2; l++) {
        float4 z = zp[lane * 2 + l];
        float4 q = qp[lane * 2 + l];
        float dx = q.x - z.x, dy = q.y - z.y, dz = q.z - z.z, dw4 = q.w - z.w;
        float4 o;
        o.x = z.x + dx; o.y = z.y + dy; o.z = z.z + dz; o.w = z.w + dw4;
        op[lane * 2 + l] = o;
        sq += dx * dx + dy * dy + dz * dz + dw4 * dw4;
        int d = (lane * 2 + l) * 4;
        atomicAdd(&g_dw[ci * DIM + d + 0], z.x);
        atomicAdd(&g_dw[ci * DIM + d + 1], z.y);
        atomicAdd(&g_dw[ci * DIM + d + 2], z.z);
        atomicAdd(&g_dw[ci * DIM + d + 3], z.w);
    }
#pragma unroll
    for (int o = 16; o; o >>= 1) sq += __shfl_down_sync(0xffffffffu, sq, o);
    if (lane == 0) {
        atomicAdd(&g_loss, (double)sq);
        atomicAdd(&g_cs[ci], 1.0f);
        out[OFF_IDX + row] = (float)ci;
    }
}

// ============================================================
// Finalize K-sized stats: new_ema_cluster_size, n, smoothed,
// perplexity, vq_loss. One block of 1024 threads.
// ============================================================
__global__ void finalize_kernel(const float* __restrict__ ecs_in,
                                float* __restrict__ out) {
    __shared__ float red[KCODES];
    int k = threadIdx.x;

    float cs   = g_cs[k];
    float necs = DECAY_F * ecs_in[k] + OMD_F * cs;
    out[OFF_ECS + k] = necs;

    // n = sum(new_ema_cluster_size)
    red[k] = necs;
    __syncthreads();
#pragma unroll
    for (int s = 512; s; s >>= 1) {
        if (k < s) red[k] += red[k + s];
        __syncthreads();
    }
    float n = red[0];
    __syncthreads();

    // perplexity terms
    float p = cs * (1.0f / (float)BATCH);
    red[k] = p * logf(p + 1e-10f);
    __syncthreads();
#pragma unroll
    for (int s = 512; s; s >>= 1) {
        if (k < s) red[k] += red[k + s];
        __syncthreads();
    }
    if (k == 0) {
        out[OFF_PERP] = expf(-red[0]);
        out[OFF_LOSS] = (float)(0.25 * (g_loss / ((double)BATCH * (double)DIM)));
    }

    float smoothed = (necs + 1e-5f) / (n + (float)(KCODES * 1e-5)) * n;
    g_smoothed[k] = smoothed;
}

// ============================================================
// new_ema_w and new_embedding. One block per code.
// ============================================================
__global__ void emaw_kernel(const float* __restrict__ ema_w,
                            float* __restrict__ out) {
    int idx = blockIdx.x * DIM + threadIdx.x;
    int k   = idx >> 8;
    float w = DECAY_F * ema_w[idx] + OMD_F * g_dw[idx];
    out[OFF_EMAW + idx] = w;
    out[OFF_EMB + idx]  = w / g_smoothed[k];
}

// ============================================================
extern "C" void kernel_launch(void* const* d_in, const int* in_sizes, int n_in,
                              void* d_out, int out_size) {
    const float* z_e  = (const float*)d_in[0];
    const float* emb  = (const float*)d_in[1];
    const float* ecs  = (const float*)d_in[2];
    const float* emaw = (const float*)d_in[3];
    float* out = (float*)d_out;

    init_kernel<<<(KCODES * DIM + 255) / 256, 256>>>();
    rowsq_kernel<<<(BATCH + KCODES) / 8, 256>>>(z_e, emb);
    argmin_kernel<<<BATCH / BM, 256>>>(z_e, emb);
    gather_kernel<<<BATCH / 8, 256>>>(z_e, emb, out);
    finalize_kernel<<<1, KCODES>>>(ecs, out);
    emaw_kernel<<<KCODES, DIM>>>(emaw, out);
}